// round 13
// baseline (speedup 1.0000x reference)
#include <cuda_runtime.h>
#include <cuda_fp16.h>
#include <stdint.h>

#define NN 8192
#define NITER 50
#define CSTAR 0.00390625f   /* 2^-8 */
/* decoded K = K_true * 2^-14; r scaled 2^-22, c unscaled (see k_final) */

static __device__ __align__(256) uint32_t g_K8[(size_t)NN * NN / 4];
static __device__ __align__(16) float g_c[(NITER + 1) * NN];  // atomic slices
static __device__ __align__(16) float g_rf[NN];
static __device__ float g_trow[NN];
static __device__ float g_tcol[NN];
static __device__ float g_S1[1];

static __device__ __forceinline__ __half2 u2h(uint32_t x) {
    return *reinterpret_cast<__half2*>(&x);
}
// two e4m3 bytes (sign=0) -> half2 of value*2^-8, exact (incl. subnormals)
static __device__ __forceinline__ __half2 dE(uint32_t q) {  // bytes 0,2
    return u2h((q << 7) & 0x7F807F80u);
}
static __device__ __forceinline__ __half2 dO(uint32_t q) {  // bytes 1,3
    return u2h((q >> 1) & 0x7F807F80u);
}
static __device__ __forceinline__ float ex2f(float x) {
    float r; asm("ex2.approx.f32 %0, %1;" : "=f"(r) : "f"(x)); return r;
}
static __device__ __forceinline__ uint32_t packh2(float a, float b) {
    const uint32_t ua = __half_as_ushort(__float2half_rn(a));
    const uint32_t ub = __half_as_ushort(__float2half_rn(b));
    return ua | (ub << 16);
}
static __device__ __forceinline__ uint32_t smem_u32(const void* p) {
    uint32_t r;
    asm("{ .reg .u64 t; cvta.to.shared.u64 t, %1; cvt.u32.u64 %0, t; }"
        : "=r"(r) : "l"(p));
    return r;
}

#define MBAR_INIT(a, c) \
    asm volatile("mbarrier.init.shared.b64 [%0], %1;" :: "r"(a), "r"(c) : "memory")
#define MBAR_EXPECT(a, b) \
    asm volatile("mbarrier.arrive.expect_tx.shared.b64 _, [%0], %1;" \
                 :: "r"(a), "r"(b) : "memory")
#define BULKCP(d, s, b, m) \
    asm volatile("cp.async.bulk.shared::cluster.global.mbarrier::complete_tx::bytes " \
                 "[%0], [%1], %2, [%3];" \
                 :: "r"(d), "l"(s), "r"(b), "r"(m) : "memory")

static __device__ __forceinline__ void mbar_wait(uint32_t m, uint32_t p) {
    asm volatile(
        "{\n\t.reg .pred P;\n\t"
        "LW%=:\n\t"
        "mbarrier.try_wait.parity.acquire.cta.shared::cta.b64 P, [%0], %1, 0x989680;\n\t"
        "@P bra.uni LD%=;\n\t"
        "bra.uni LW%=;\n\t"
        "LD%=:\n\t}"
        :: "r"(m), "r"(p) : "memory");
}

// ---------------------------------------------------------------------------
__global__ void k_init() {
    const int n = (NITER + 1) * NN;   // 417792 == 1632*256
    for (int i = blockIdx.x * blockDim.x + threadIdx.x; i < n;
         i += gridDim.x * blockDim.x) {
        g_c[i] = (i < NN) ? 1.0f : 0.0f;
        if (i < NN) { g_trow[i] = 0.0f; g_tcol[i] = 0.0f; }
        if (i == 0) g_S1[0] = 0.0f;
    }
}

// ---------------------------------------------------------------------------
// fused build + target reductions (proven)
// ---------------------------------------------------------------------------
__global__ void __launch_bounds__(256) k_bt(const float* __restrict__ M,
                                            const float* __restrict__ tgt) {
    const int r0 = blockIdx.y << 7;
    const int c0 = blockIdx.x << 10;
    const int t  = threadIdx.x;
    const int lane = t & 31;
    const float4* __restrict__ pm =
        (const float4*)(M + (size_t)r0 * NN + c0) + t;
    const float4* __restrict__ pt =
        (const float4*)(tgt + (size_t)r0 * NN + c0) + t;
    uint32_t* __restrict__ pk = g_K8 + (size_t)r0 * (NN / 4) + (c0 >> 2) + t;

    float cx = 0.f, cy = 0.f, cz = 0.f, cw = 0.f, dot = 0.f;
    for (int r = 0; r < 128; r++) {
        const float4 m4 = pm[r * (NN / 4)];
        const float4 t4 = pt[r * (NN / 4)];
        const float e0 = ex2f(fmaf(14.42695041f, m4.x, -6.0f));
        const float e1 = ex2f(fmaf(14.42695041f, m4.y, -6.0f));
        const float e2 = ex2f(fmaf(14.42695041f, m4.z, -6.0f));
        const float e3 = ex2f(fmaf(14.42695041f, m4.w, -6.0f));
        unsigned short lo, hi;
        asm("cvt.rn.satfinite.e4m3x2.f32 %0, %1, %2;" : "=h"(lo) : "f"(e1), "f"(e0));
        asm("cvt.rn.satfinite.e4m3x2.f32 %0, %1, %2;" : "=h"(hi) : "f"(e3), "f"(e2));
        pk[r * (NN / 4)] = (uint32_t)lo | ((uint32_t)hi << 16);

        cx += t4.x; cy += t4.y; cz += t4.z; cw += t4.w;
        dot = fmaf(t4.x, m4.x, dot);
        dot = fmaf(t4.y, m4.y, dot);
        dot = fmaf(t4.z, m4.z, dot);
        dot = fmaf(t4.w, m4.w, dot);
        float s4 = (t4.x + t4.y) + (t4.z + t4.w);
#pragma unroll
        for (int o = 16; o; o >>= 1)
            s4 += __shfl_xor_sync(0xFFFFFFFFu, s4, o);
        if (lane == 0) atomicAdd(&g_trow[r0 + r], s4);
    }
    float* tc = g_tcol + c0 + (t << 2);
    atomicAdd(tc + 0, cx);
    atomicAdd(tc + 1, cy);
    atomicAdd(tc + 2, cz);
    atomicAdd(tc + 3, cw);

    __shared__ float sred[256];
    sred[t] = dot;
    __syncthreads();
    for (int s = 128; s > 0; s >>= 1) {
        if (t < s) sred[t] += sred[t + s];
        __syncthreads();
    }
    if (t == 0) atomicAdd(&g_S1[0], sred[0]);
}

// ---------------------------------------------------------------------------
// passA: r[i] = sum_j Kd[i,j] * (CSTAR / c[j])
// 256 blocks x 256 thr (one wave, 2/SM). Block = 32 rows; chunk = 4 rows
// = ONE contiguous 32 KB cp.async.bulk; double-buffered with mbarriers.
// Warp w owns cols [w*1024,(w+1)*1024); lane's 32 cols (2 non-adjacent
// uint4) have their 16 half2 weights in REGISTERS (no weight table).
// ---------------------------------------------------------------------------
#define SMEM_A_DYN 65680
__global__ void __launch_bounds__(256, 2) k_passA(const float* __restrict__ vin,
                                                  float* __restrict__ vout) {
    extern __shared__ __align__(128) char smem[];
    const uint32_t sb = smem_u32(smem);
    const int t = threadIdx.x, w = t >> 5, lane = t & 31;
    const int row0 = blockIdx.x << 5;
    const uint32_t mb0 = sb + 65536u, mb1 = sb + 65544u;
    float* r_sm = (float*)(smem + 65552);

    // per-lane weights: cols w*1024 + lane*16 (+0..15) -> wA; +512 -> wB
    uint32_t wA[8], wB[8];
    {
        const float4* pA = (const float4*)(vin + (w << 10) + (lane << 4));
        const float4* pB = (const float4*)(vin + (w << 10) + (lane << 4) + 512);
#pragma unroll
        for (int j = 0; j < 4; j++) {
            const float4 fa = pA[j];
            wA[2 * j]     = packh2(__fdividef(CSTAR, fa.x), __fdividef(CSTAR, fa.z));
            wA[2 * j + 1] = packh2(__fdividef(CSTAR, fa.y), __fdividef(CSTAR, fa.w));
            const float4 fb = pB[j];
            wB[2 * j]     = packh2(__fdividef(CSTAR, fb.x), __fdividef(CSTAR, fb.z));
            wB[2 * j + 1] = packh2(__fdividef(CSTAR, fb.y), __fdividef(CSTAR, fb.w));
        }
    }
    if (t < 32) r_sm[t] = 0.0f;
    if (t == 0) { MBAR_INIT(mb0, 1u); MBAR_INIT(mb1, 1u); }
    __syncthreads();

    const char* src = (const char*)g_K8 + ((size_t)row0 << 13);
    if (t == 0) {
        MBAR_EXPECT(mb0, 32768u); BULKCP(sb, src, 32768u, mb0);
        MBAR_EXPECT(mb1, 32768u); BULKCP(sb + 32768u, src + 32768, 32768u, mb1);
    }

    const char* bp0 = smem + (w << 10) + (lane << 4);
    for (int k = 0; k < 8; k++) {
        const uint32_t mb = (k & 1) ? mb1 : mb0;
        const uint32_t bo = (k & 1) ? 32768u : 0u;
        mbar_wait(mb, (unsigned)((k >> 1) & 1));
        const char* bp = bp0 + bo;
#pragma unroll
        for (int r = 0; r < 4; r++) {
            const uint4 qa = *(const uint4*)(bp + (r << 13));
            const uint4 qb = *(const uint4*)(bp + (r << 13) + 512);
            const __half2 z = __floats2half2_rn(0.f, 0.f);
            __half2 h0 = z, h1 = z, h2 = z, h3 = z;
            h0 = __hfma2(dE(qa.x), u2h(wA[0]), h0);
            h1 = __hfma2(dO(qa.x), u2h(wA[1]), h1);
            h2 = __hfma2(dE(qa.y), u2h(wA[2]), h2);
            h3 = __hfma2(dO(qa.y), u2h(wA[3]), h3);
            h0 = __hfma2(dE(qa.z), u2h(wA[4]), h0);
            h1 = __hfma2(dO(qa.z), u2h(wA[5]), h1);
            h2 = __hfma2(dE(qa.w), u2h(wA[6]), h2);
            h3 = __hfma2(dO(qa.w), u2h(wA[7]), h3);
            h0 = __hfma2(dE(qb.x), u2h(wB[0]), h0);
            h1 = __hfma2(dO(qb.x), u2h(wB[1]), h1);
            h2 = __hfma2(dE(qb.y), u2h(wB[2]), h2);
            h3 = __hfma2(dO(qb.y), u2h(wB[3]), h3);
            h0 = __hfma2(dE(qb.z), u2h(wB[4]), h0);
            h1 = __hfma2(dO(qb.z), u2h(wB[5]), h1);
            h2 = __hfma2(dE(qb.w), u2h(wB[6]), h2);
            h3 = __hfma2(dO(qb.w), u2h(wB[7]), h3);
            const __half2 hs = __hadd2(__hadd2(h0, h1), __hadd2(h2, h3));
            float v = __low2float(hs) + __high2float(hs);
#pragma unroll
            for (int o = 16; o; o >>= 1)
                v += __shfl_xor_sync(0xFFFFFFFFu, v, o);
            if (lane == 0) atomicAdd(&r_sm[(k << 2) + r], v);
        }
        __syncthreads();
        if (k < 6 && t == 0) {
            MBAR_EXPECT(mb, 32768u);
            BULKCP(sb + bo, src + ((size_t)(k + 2) << 15), 32768u, mb);
        }
    }
    if (t < 32) vout[row0 + t] = r_sm[t];
}

// ---------------------------------------------------------------------------
// passB: c[j] += sum_{i in 64-row group} Kd[i,j] * (CSTAR / r[i])
// grid (2,128) = 256 blocks (one wave). Block = 64 rows x 4096 cols;
// chunk = 8 rows (8 x 4KB bulk copies), double-buffered. Thread t owns
// uint4 col t; chains flushed every 32 rows; 16 atomics into zeroed c.
// ---------------------------------------------------------------------------
#define SMEM_B_DYN 65808
__global__ void __launch_bounds__(256, 2) k_passB(const float* __restrict__ vin,
                                                  float* __restrict__ vout) {
    extern __shared__ __align__(128) char smem[];
    const uint32_t sb = smem_u32(smem);
    const int t = threadIdx.x;
    const int r0 = blockIdx.y << 6;
    const int colbase = blockIdx.x << 12;
    const uint32_t mb0 = sb + 65536u, mb1 = sb + 65544u;
    uint32_t* swr = (uint32_t*)(smem + 65552);
    if (t < 64) {
        const float wv = __fdividef(CSTAR, vin[r0 + t]);
        swr[t] = packh2(wv, wv);
    }
    if (t == 0) { MBAR_INIT(mb0, 1u); MBAR_INIT(mb1, 1u); }
    __syncthreads();

    const char* src = (const char*)g_K8 + ((size_t)r0 << 13) + colbase;
    if (t == 0) {
        MBAR_EXPECT(mb0, 32768u);
#pragma unroll
        for (int j = 0; j < 8; j++)
            BULKCP(sb + j * 4096u, src + ((size_t)j << 13), 4096u, mb0);
        MBAR_EXPECT(mb1, 32768u);
#pragma unroll
        for (int j = 0; j < 8; j++)
            BULKCP(sb + 32768u + j * 4096u, src + ((size_t)(8 + j) << 13),
                   4096u, mb1);
    }

    const __half2 z = __floats2half2_rn(0.f, 0.f);
    __half2 A0 = z, A1 = z, A2 = z, A3 = z, A4 = z, A5 = z, A6 = z, A7 = z;
    float f[16];
#pragma unroll
    for (int j = 0; j < 16; j++) f[j] = 0.0f;

    const char* bp0 = smem + (t << 4);
    for (int k = 0; k < 8; k++) {
        const uint32_t mb = (k & 1) ? mb1 : mb0;
        const uint32_t bo = (k & 1) ? 32768u : 0u;
        mbar_wait(mb, (unsigned)((k >> 1) & 1));
        const char* bp = bp0 + bo;
        uint4 q[8];
#pragma unroll
        for (int j = 0; j < 8; j++)
            q[j] = *(const uint4*)(bp + (j << 12));
#pragma unroll
        for (int j = 0; j < 8; j++) {
            const __half2 wr = u2h(swr[(k << 3) + j]);
            A0 = __hfma2(dE(q[j].x), wr, A0);
            A1 = __hfma2(dO(q[j].x), wr, A1);
            A2 = __hfma2(dE(q[j].y), wr, A2);
            A3 = __hfma2(dO(q[j].y), wr, A3);
            A4 = __hfma2(dE(q[j].z), wr, A4);
            A5 = __hfma2(dO(q[j].z), wr, A5);
            A6 = __hfma2(dE(q[j].w), wr, A6);
            A7 = __hfma2(dO(q[j].w), wr, A7);
        }
        if (k == 3 || k == 7) {   // flush every 32 rows (chain cap = 32)
            f[0]  += __low2float(A0);   f[2]  += __high2float(A0);
            f[1]  += __low2float(A1);   f[3]  += __high2float(A1);
            f[4]  += __low2float(A2);   f[6]  += __high2float(A2);
            f[5]  += __low2float(A3);   f[7]  += __high2float(A3);
            f[8]  += __low2float(A4);   f[10] += __high2float(A4);
            f[9]  += __low2float(A5);   f[11] += __high2float(A5);
            f[12] += __low2float(A6);   f[14] += __high2float(A6);
            f[13] += __low2float(A7);   f[15] += __high2float(A7);
            A0 = z; A1 = z; A2 = z; A3 = z;
            A4 = z; A5 = z; A6 = z; A7 = z;
        }
        __syncthreads();
        if (k < 6 && t == 0) {
            MBAR_EXPECT(mb, 32768u);
#pragma unroll
            for (int j = 0; j < 8; j++)
                BULKCP(sb + bo + j * 4096u,
                       src + ((size_t)((k + 2) * 8 + j) << 13), 4096u, mb);
        }
    }

    float* vo = vout + colbase + (t << 4);
#pragma unroll
    for (int j = 0; j < 16; j++) atomicAdd(vo + j, f[j]);
}

// ---------------------------------------------------------------------------
// loss = -10*S1 + 35*ln2*S3 + <trow, ln r50> + <tcol, ln c50>
// ---------------------------------------------------------------------------
__global__ void __launch_bounds__(1024) k_final(float* __restrict__ out) {
    const int t = threadIdx.x;
    const float* cfin = g_c + (size_t)NITER * NN;
    float s1 = 0.f, s2 = 0.f, s3 = 0.f;
    for (int i = t; i < NN; i += 1024) {
        const float tr = g_trow[i];
        s1 += tr * __logf(g_rf[i]);
        s3 += tr;
        s2 += g_tcol[i] * __logf(cfin[i]);
    }
    __shared__ float sa[1024], sb[1024], sc[1024];
    sa[t] = s1; sb[t] = s2; sc[t] = s3;
    __syncthreads();
    for (int s = 512; s > 0; s >>= 1) {
        if (t < s) { sa[t] += sa[t + s]; sb[t] += sb[t + s]; sc[t] += sc[t + s]; }
        __syncthreads();
    }
    if (t == 0)
        out[0] = -10.0f * g_S1[0] + 24.260151319598086f * sc[0] + sa[0] + sb[0];
}

// ---------------------------------------------------------------------------
extern "C" void kernel_launch(void* const* d_in, const int* in_sizes, int n_in,
                              void* d_out, int out_size) {
    (void)in_sizes; (void)n_in; (void)out_size;
    const float* M   = (const float*)d_in[0];
    const float* tgt = (const float*)d_in[1];
    float* out = (float*)d_out;

    cudaFuncSetAttribute(k_passA, cudaFuncAttributeMaxDynamicSharedMemorySize,
                         SMEM_A_DYN);
    cudaFuncSetAttribute(k_passB, cudaFuncAttributeMaxDynamicSharedMemorySize,
                         SMEM_B_DYN);

    void *pC, *pR;
    cudaGetSymbolAddress(&pC, g_c);
    cudaGetSymbolAddress(&pR, g_rf);
    float* C  = (float*)pC;
    float* RF = (float*)pR;

    k_init<<<1632, 256>>>();
    k_bt<<<dim3(8, 64), 256>>>(M, tgt);

    for (int k = 1; k <= NITER; k++) {
        k_passA<<<256, 256, SMEM_A_DYN>>>(C + (size_t)(k - 1) * NN, RF);
        k_passB<<<dim3(2, 128), 256, SMEM_B_DYN>>>(RF, C + (size_t)k * NN);
    }
    k_final<<<1, 1024>>>(out);
}

// round 14
// speedup vs baseline: 1.1475x; 1.1475x over previous
#include <cuda_runtime.h>
#include <cuda_fp16.h>
#include <stdint.h>

#define NN 8192
#define NITER 50
#define CSTAR 0.00390625f   /* 2^-8 */
/* decoded K = K_true * 2^-14; r scaled 2^-22, c unscaled (see k_final) */

static __device__ __align__(256) uint32_t g_K8[(size_t)NN * NN / 4];
static __device__ __align__(16) float g_c[(NITER + 1) * NN];  // atomic slices
static __device__ __align__(16) float g_rf[NN];
static __device__ __align__(16) uint32_t g_wc[NN / 2];  // packed half2 weights
static __device__ float g_trow[NN];
static __device__ float g_tcol[NN];
static __device__ float g_S1[1];

static __device__ __forceinline__ __half2 u2h(uint32_t x) {
    return *reinterpret_cast<__half2*>(&x);
}
// two e4m3 bytes (sign=0) -> half2 of value*2^-8, exact (incl. subnormals)
static __device__ __forceinline__ __half2 dE(uint32_t q) {  // bytes 0,2
    return u2h((q << 7) & 0x7F807F80u);
}
static __device__ __forceinline__ __half2 dO(uint32_t q) {  // bytes 1,3
    return u2h((q >> 1) & 0x7F807F80u);
}
static __device__ __forceinline__ float ex2f(float x) {
    float r; asm("ex2.approx.f32 %0, %1;" : "=f"(r) : "f"(x)); return r;
}
static __device__ __forceinline__ uint32_t packh2(float a, float b) {
    const uint32_t ua = __half_as_ushort(__float2half_rn(a));
    const uint32_t ub = __half_as_ushort(__float2half_rn(b));
    return ua | (ub << 16);
}

// ---------------------------------------------------------------------------
__global__ void k_init() {
    const int n = (NITER + 1) * NN;   // 417792 == 1632*256
    for (int i = blockIdx.x * blockDim.x + threadIdx.x; i < n;
         i += gridDim.x * blockDim.x) {
        g_c[i] = (i < NN) ? 1.0f : 0.0f;
        if (i < NN) { g_trow[i] = 0.0f; g_tcol[i] = 0.0f; }
        if (i < NN / 2) g_wc[i] = 0x1C001C00u;   // half2(2^-8,2^-8): c0 = 1
        if (i == 0) g_S1[0] = 0.0f;
    }
}

// ---------------------------------------------------------------------------
// k_wc: build next iteration's column-weight table ONCE (was redundantly
// rebuilt by every passA block = 2M MUFU.RCP/pass; now 8192 total).
// Pair-shuffled layout identical to the old in-block prologue:
//   g_wc[2g]   = packh2(w[4g],   w[4g+2])
//   g_wc[2g+1] = packh2(w[4g+1], w[4g+3])
// ---------------------------------------------------------------------------
__global__ void __launch_bounds__(128) k_wc(const float* __restrict__ vin) {
    const int g = blockIdx.x * 128 + threadIdx.x;   // 0..2047 (float4 groups)
    const float4 c4 = ((const float4*)vin)[g];
    g_wc[2 * g]     = packh2(__fdividef(CSTAR, c4.x), __fdividef(CSTAR, c4.z));
    g_wc[2 * g + 1] = packh2(__fdividef(CSTAR, c4.y), __fdividef(CSTAR, c4.w));
}

// ---------------------------------------------------------------------------
// fused build + target reductions (proven)
// ---------------------------------------------------------------------------
__global__ void __launch_bounds__(256) k_bt(const float* __restrict__ M,
                                            const float* __restrict__ tgt) {
    const int r0 = blockIdx.y << 7;
    const int c0 = blockIdx.x << 10;
    const int t  = threadIdx.x;
    const int lane = t & 31;
    const float4* __restrict__ pm =
        (const float4*)(M + (size_t)r0 * NN + c0) + t;
    const float4* __restrict__ pt =
        (const float4*)(tgt + (size_t)r0 * NN + c0) + t;
    uint32_t* __restrict__ pk = g_K8 + (size_t)r0 * (NN / 4) + (c0 >> 2) + t;

    float cx = 0.f, cy = 0.f, cz = 0.f, cw = 0.f, dot = 0.f;
    for (int r = 0; r < 128; r++) {
        const float4 m4 = pm[r * (NN / 4)];
        const float4 t4 = pt[r * (NN / 4)];
        const float e0 = ex2f(fmaf(14.42695041f, m4.x, -6.0f));
        const float e1 = ex2f(fmaf(14.42695041f, m4.y, -6.0f));
        const float e2 = ex2f(fmaf(14.42695041f, m4.z, -6.0f));
        const float e3 = ex2f(fmaf(14.42695041f, m4.w, -6.0f));
        unsigned short lo, hi;
        asm("cvt.rn.satfinite.e4m3x2.f32 %0, %1, %2;" : "=h"(lo) : "f"(e1), "f"(e0));
        asm("cvt.rn.satfinite.e4m3x2.f32 %0, %1, %2;" : "=h"(hi) : "f"(e3), "f"(e2));
        pk[r * (NN / 4)] = (uint32_t)lo | ((uint32_t)hi << 16);

        cx += t4.x; cy += t4.y; cz += t4.z; cw += t4.w;
        dot = fmaf(t4.x, m4.x, dot);
        dot = fmaf(t4.y, m4.y, dot);
        dot = fmaf(t4.z, m4.z, dot);
        dot = fmaf(t4.w, m4.w, dot);
        float s4 = (t4.x + t4.y) + (t4.z + t4.w);
#pragma unroll
        for (int o = 16; o; o >>= 1)
            s4 += __shfl_xor_sync(0xFFFFFFFFu, s4, o);
        if (lane == 0) atomicAdd(&g_trow[r0 + r], s4);
    }
    float* tc = g_tcol + c0 + (t << 2);
    atomicAdd(tc + 0, cx);
    atomicAdd(tc + 1, cy);
    atomicAdd(tc + 2, cz);
    atomicAdd(tc + 3, cw);

    __shared__ float sred[256];
    sred[t] = dot;
    __syncthreads();
    for (int s = 128; s > 0; s >>= 1) {
        if (t < s) sred[t] += sred[t + s];
        __syncthreads();
    }
    if (t == 0) atomicAdd(&g_S1[0], sred[0]);
}

// ---------------------------------------------------------------------------
// two-row dot sweep over full 8192 cols (R7/R11 pattern, proven)
// ---------------------------------------------------------------------------
static __device__ __forceinline__ void sweep2(
    const uint4* __restrict__ base, const uint4* __restrict__ swv,
    float& va, float& vb)
{
    const uint4* pa = base;
    const uint4* pb = base + (NN / 16);
    const __half2 z = __floats2half2_rn(0.f, 0.f);
    __half2 aE0 = z, aO0 = z, aE1 = z, aO1 = z;
    __half2 bE0 = z, bO0 = z, bE1 = z, bO1 = z;

#pragma unroll 2
    for (int s = 0; s < 16; s += 4) {
        uint4 qa[4], qb[4];
#pragma unroll
        for (int j = 0; j < 4; j++) {
            qa[j] = pa[(s + j) * 32];
            qb[j] = pb[(s + j) * 32];
        }
#pragma unroll
        for (int j = 0; j < 4; j++) {
            const uint4 w0 = swv[(s + j) << 6];
            const uint4 w1 = swv[((s + j) << 6) + 1];
            aE0 = __hfma2(dE(qa[j].x), u2h(w0.x), aE0);
            aO0 = __hfma2(dO(qa[j].x), u2h(w0.y), aO0);
            aE1 = __hfma2(dE(qa[j].y), u2h(w0.z), aE1);
            aO1 = __hfma2(dO(qa[j].y), u2h(w0.w), aO1);
            aE0 = __hfma2(dE(qa[j].z), u2h(w1.x), aE0);
            aO0 = __hfma2(dO(qa[j].z), u2h(w1.y), aO0);
            aE1 = __hfma2(dE(qa[j].w), u2h(w1.z), aE1);
            aO1 = __hfma2(dO(qa[j].w), u2h(w1.w), aO1);
            bE0 = __hfma2(dE(qb[j].x), u2h(w0.x), bE0);
            bO0 = __hfma2(dO(qb[j].x), u2h(w0.y), bO0);
            bE1 = __hfma2(dE(qb[j].y), u2h(w0.z), bE1);
            bO1 = __hfma2(dO(qb[j].y), u2h(w0.w), bO1);
            bE0 = __hfma2(dE(qb[j].z), u2h(w1.x), bE0);
            bO0 = __hfma2(dO(qb[j].z), u2h(w1.y), bO0);
            bE1 = __hfma2(dE(qb[j].w), u2h(w1.z), bE1);
            bO1 = __hfma2(dO(qb[j].w), u2h(w1.w), bO1);
        }
    }
    __half2 sa = __hadd2(__hadd2(aE0, aO0), __hadd2(aE1, aO1));
    __half2 sb = __hadd2(__hadd2(bE0, bO0), __hadd2(bE1, bO1));
    va = __low2float(sa) + __high2float(sa);
    vb = __low2float(sb) + __high2float(sb);
#pragma unroll
    for (int o = 16; o; o >>= 1) {
        va += __shfl_xor_sync(0xFFFFFFFFu, va, o);
        vb += __shfl_xor_sync(0xFFFFFFFFu, vb, o);
    }
}

// ---------------------------------------------------------------------------
// passA: r[i] = sum_j Kd[i,j] * wc[j]
// 256 blocks x 256 thr -> ONE wave. Block = 32 rows. Prologue is now a
// 16 KB coalesced table copy (was 8192 redundant MUFU divides per block).
// ---------------------------------------------------------------------------
__global__ void __launch_bounds__(256, 2) k_passA(float* __restrict__ vout) {
    __shared__ uint32_t sw[4096];
    const int t = threadIdx.x;
#pragma unroll
    for (int j = 0; j < 4; j++)
        ((uint4*)sw)[t + (j << 8)] = ((const uint4*)g_wc)[t + (j << 8)];
    __syncthreads();

    const int w = t >> 5, lane = t & 31;
    const int row0 = blockIdx.x << 5;
    const uint4* swv = ((const uint4*)sw) + (lane << 1);

#pragma unroll
    for (int half = 0; half < 2; half++) {
        const int rowa = row0 + (half << 4) + (w << 1);
        const uint4* base =
            ((const uint4*)g_K8) + (size_t)rowa * (NN / 16) + lane;
        float va, vb;
        sweep2(base, swv, va, vb);
        if (lane == 0) {
            vout[rowa]     = va;
            vout[rowa + 1] = vb;
        }
    }
}

// ---------------------------------------------------------------------------
// passB: c[j] += sum_{i in 64-row group} Kd[i,j] * (CSTAR / r[i])
// grid (2, 128) = 256 blocks -> ONE wave (prologue = 64 divides, negligible).
// ---------------------------------------------------------------------------
__global__ void __launch_bounds__(256, 2) k_passB(const float* __restrict__ vin,
                                                  float* __restrict__ vout) {
    __shared__ uint32_t swr[64];
    const int t  = threadIdx.x;
    const int r0 = blockIdx.y << 6;
    const int cc = (blockIdx.x << 8) + t;     // uint4 chunk index 0..511
    if (t < 64) {
        const float wv = __fdividef(CSTAR, vin[r0 + t]);
        swr[t] = packh2(wv, wv);
    }
    __syncthreads();

    const uint4* __restrict__ base =
        ((const uint4*)g_K8) + (size_t)r0 * (NN / 16) + cc;

    const __half2 z = __floats2half2_rn(0.f, 0.f);
    __half2 A0 = z, A1 = z, A2 = z, A3 = z;
    __half2 A4 = z, A5 = z, A6 = z, A7 = z;
    float f[16];
#pragma unroll
    for (int j = 0; j < 16; j++) f[j] = 0.0f;

#pragma unroll
    for (int b = 0; b < 8; b++) {
        uint4 q[8];
#pragma unroll
        for (int j = 0; j < 8; j++)
            q[j] = base[(size_t)((b << 3) + j) * (NN / 16)];
#pragma unroll
        for (int j = 0; j < 8; j++) {
            const __half2 wr = u2h(swr[(b << 3) + j]);
            A0 = __hfma2(dE(q[j].x), wr, A0);
            A1 = __hfma2(dO(q[j].x), wr, A1);
            A2 = __hfma2(dE(q[j].y), wr, A2);
            A3 = __hfma2(dO(q[j].y), wr, A3);
            A4 = __hfma2(dE(q[j].z), wr, A4);
            A5 = __hfma2(dO(q[j].z), wr, A5);
            A6 = __hfma2(dE(q[j].w), wr, A6);
            A7 = __hfma2(dO(q[j].w), wr, A7);
        }
        if (b == 3 || b == 7) {   // flush every 32 rows (chain cap = 32)
            f[0]  += __low2float(A0);   f[2]  += __high2float(A0);
            f[1]  += __low2float(A1);   f[3]  += __high2float(A1);
            f[4]  += __low2float(A2);   f[6]  += __high2float(A2);
            f[5]  += __low2float(A3);   f[7]  += __high2float(A3);
            f[8]  += __low2float(A4);   f[10] += __high2float(A4);
            f[9]  += __low2float(A5);   f[11] += __high2float(A5);
            f[12] += __low2float(A6);   f[14] += __high2float(A6);
            f[13] += __low2float(A7);   f[15] += __high2float(A7);
            A0 = z; A1 = z; A2 = z; A3 = z;
            A4 = z; A5 = z; A6 = z; A7 = z;
        }
    }

    float* vo = vout + (cc << 4);
#pragma unroll
    for (int j = 0; j < 16; j++) atomicAdd(vo + j, f[j]);
}

// ---------------------------------------------------------------------------
// loss = -10*S1 + 35*ln2*S3 + <trow, ln r50> + <tcol, ln c50>
// ---------------------------------------------------------------------------
__global__ void __launch_bounds__(1024) k_final(float* __restrict__ out) {
    const int t = threadIdx.x;
    const float* cfin = g_c + (size_t)NITER * NN;
    float s1 = 0.f, s2 = 0.f, s3 = 0.f;
    for (int i = t; i < NN; i += 1024) {
        const float tr = g_trow[i];
        s1 += tr * __logf(g_rf[i]);
        s3 += tr;
        s2 += g_tcol[i] * __logf(cfin[i]);
    }
    __shared__ float sa[1024], sb[1024], sc[1024];
    sa[t] = s1; sb[t] = s2; sc[t] = s3;
    __syncthreads();
    for (int s = 512; s > 0; s >>= 1) {
        if (t < s) { sa[t] += sa[t + s]; sb[t] += sb[t + s]; sc[t] += sc[t + s]; }
        __syncthreads();
    }
    if (t == 0)
        out[0] = -10.0f * g_S1[0] + 24.260151319598086f * sc[0] + sa[0] + sb[0];
}

// ---------------------------------------------------------------------------
extern "C" void kernel_launch(void* const* d_in, const int* in_sizes, int n_in,
                              void* d_out, int out_size) {
    (void)in_sizes; (void)n_in; (void)out_size;
    const float* M   = (const float*)d_in[0];
    const float* tgt = (const float*)d_in[1];
    float* out = (float*)d_out;

    void *pC, *pR;
    cudaGetSymbolAddress(&pC, g_c);
    cudaGetSymbolAddress(&pR, g_rf);
    float* C  = (float*)pC;
    float* RF = (float*)pR;

    k_init<<<1632, 256>>>();
    k_bt<<<dim3(8, 64), 256>>>(M, tgt);

    for (int k = 1; k <= NITER; k++) {
        k_passA<<<256, 256>>>(RF);
        k_passB<<<dim3(2, 128), 256>>>(RF, C + (size_t)k * NN);
        if (k < NITER) k_wc<<<16, 128>>>(C + (size_t)k * NN);
    }
    k_final<<<1, 1024>>>(out);
}